// round 9
// baseline (speedup 1.0000x reference)
#include <cuda_runtime.h>
#include <cuda_fp16.h>

#define N_NODES 50000
#define N_EDGES 600000
#define DIM 128
#define OUTD 64

#define PADA 136   // words per row (k-stride); mod 32 = 8 -> conflict-free LDS.64
#define PADB 72    // words per row for 64-K B chunks; mod 32 = 8 -> conflict-free

// ---- scratch (static device globals; no runtime allocation) ----
__device__ __half2   g_msg[N_NODES * 64];   // fp16 messages (128 per node)
__device__ float     g_h[N_NODES * DIM];
__device__ int       g_deg[N_NODES];
__device__ int       g_off[N_NODES];
__device__ int       g_cur[N_NODES];
__device__ int       g_ctr;
__device__ int       g_csr_src[N_EDGES];
__device__ unsigned  g_Bt1[2 * 192 * 128];  // layer-1 weights, tf32, k-permuted, usage order
__device__ unsigned  g_Bt2[2 * 192 * 128];  // layer-2 weights
__device__ unsigned  g_Bp[64 * 128];        // Wp, tf32 (unpermuted)

// ============================ helpers ============================

__device__ __forceinline__ unsigned f2tf32(float f) {
    unsigned u;
    asm("cvt.rna.tf32.f32 %0, %1;" : "=r"(u) : "f"(f));
    return u;
}

__device__ __forceinline__ void mma_tf32(float* c,
                                         unsigned a0, unsigned a1, unsigned a2, unsigned a3,
                                         unsigned b0, unsigned b1) {
    asm volatile(
        "mma.sync.aligned.m16n8k8.row.col.f32.tf32.tf32.f32 "
        "{%0,%1,%2,%3}, {%4,%5,%6,%7}, {%8,%9}, {%0,%1,%2,%3};"
        : "+f"(c[0]), "+f"(c[1]), "+f"(c[2]), "+f"(c[3])
        : "r"(a0), "r"(a1), "r"(a2), "r"(a3), "r"(b0), "r"(b1));
}

__device__ __forceinline__ void cp_async16(unsigned smem_addr, const void* gptr) {
    asm volatile("cp.async.cg.shared.global [%0], [%1], 16;"
                 :: "r"(smem_addr), "l"(gptr));
}
#define CP_COMMIT() asm volatile("cp.async.commit_group;" ::: "memory")
#define CP_WAIT0()  asm volatile("cp.async.wait_group 0;" ::: "memory")

// ============================ CSR build ============================

__global__ void zero_deg_kernel() {
    int i = blockIdx.x * blockDim.x + threadIdx.x;
    if (i < N_NODES) g_deg[i] = 0;
    if (i == 0) g_ctr = 0;
}

__global__ void hist_kernel(const int* __restrict__ dst) {
    int e = blockIdx.x * blockDim.x + threadIdx.x;
    if (e < N_EDGES) atomicAdd(&g_deg[dst[e]], 1);
}

// unordered disjoint range claim (aggregation is order-agnostic)
__global__ void offsets_kernel() {
    int i = blockIdx.x * blockDim.x + threadIdx.x;
    if (i < N_NODES) {
        int d = g_deg[i];
        int s = atomicAdd(&g_ctr, d);
        g_off[i] = s;
        g_cur[i] = s;
    }
}

__global__ void fill_csr_kernel(const int* __restrict__ src, const int* __restrict__ dst) {
    int e = blockIdx.x * blockDim.x + threadIdx.x;
    if (e < N_EDGES) {
        int d = dst[e];
        int p = atomicAdd(&g_cur[d], 1);
        g_csr_src[p] = src[e];
    }
}

// ==================== weight pre-conversion (fp32 -> tf32, k-permuted, usage order) ====
// row order r: r<64: W[64j+r] (m); r<128: F[64j+r-64] (gamma); r<192: F[64j+r] (beta).
// k-permutation within each 8-group: original i -> slot (i&3)*2 + (i>>2).

__global__ void prep_weights(const float* __restrict__ W,
                             const float* __restrict__ F,
                             int layer) {
    unsigned* dst = layer ? g_Bt2 : g_Bt1;
    int idx = blockIdx.x * blockDim.x + threadIdx.x;   // over 2*192*32 float4 groups
    if (idx >= 2 * 192 * 32) return;
    int j  = idx / (192 * 32);
    int r  = (idx >> 5) % 192;
    int c4 = (idx & 31) * 4;
    const float* srcRow;
    if (r < 64)       srcRow = W + (64 * j + r) * 128;
    else if (r < 128) srcRow = F + (64 * j + r - 64) * 128;
    else              srcRow = F + (64 * j + r) * 128;
    float4 v = *(const float4*)(srcRow + c4);
    unsigned* p = dst + (j * 192 + r) * 128 + ((c4 >> 3) << 3) + ((c4 & 4) ? 1 : 0);
    p[0] = f2tf32(v.x); p[2] = f2tf32(v.y); p[4] = f2tf32(v.z); p[6] = f2tf32(v.w);
}

__global__ void prep_wp(const float* __restrict__ Wp) {
    int idx = blockIdx.x * blockDim.x + threadIdx.x;   // over 64*32 float4 groups
    if (idx >= 64 * 32) return;
    float4 v = *(const float4*)(Wp + idx * 4);
    unsigned* p = g_Bp + idx * 4;
    p[0] = f2tf32(v.x); p[1] = f2tf32(v.y); p[2] = f2tf32(v.z); p[3] = f2tf32(v.w);
}

// ==================== fused FiLM GEMM (tf32 tc, M=128, 512 thr, cp.async pipeline) =====
// 16 warps: wr = wid>>2 owns node rows [wr*32, +32); wc = wid&3 owns weight cols
// [wc*16, +16) of each of the 3 mats (m/gamma/beta). B staged in 4 chunks (j x kc),
// double-buffered via cp.async, overlapped with A conversion / previous chunk's MMAs.

__global__ void film_gemm_fused(const float* __restrict__ Ain, int layer) {
    extern __shared__ unsigned smem[];
    unsigned* sA  = smem;                     // 128*PADA (k-permuted)
    unsigned* sB0 = smem + 128 * PADA;        // 192*PADB
    unsigned* sB1 = sB0 + 192 * PADB;         // 192*PADB

    const float*    A  = layer ? g_h : Ain;
    const unsigned* Bt = layer ? g_Bt2 : g_Bt1;

    int tid  = threadIdx.x;     // 512
    int wid  = tid >> 5;
    int lane = tid & 31;
    int g    = lane >> 2;       // 0..7
    int tg   = lane & 3;        // 0..3
    int wr   = wid >> 2;        // 0..3 (32-row group)
    int wc   = wid & 3;         // 0..3 (16-col group per mat)
    int row0 = blockIdx.x * 128;

    unsigned sB0u = (unsigned)__cvta_generic_to_shared(sB0);
    unsigned sB1u = (unsigned)__cvta_generic_to_shared(sB1);

    // chunk issue: chunk c covers j=c>>1, kc=c&1 (192 rows x 64 K words)
    auto issue_chunk = [&](int c) {
        int jj = c >> 1, kc = c & 1;
        unsigned dstBase = (c & 1) ? sB1u : sB0u;
        const unsigned* srcBase = Bt + (jj * 192) * 128 + kc * 64;
#pragma unroll
        for (int t = 0; t < 6; t++) {
            int idx = tid + t * 512;          // 192*16 = 3072 = 6*512
            int r  = idx >> 4;
            int w4 = (idx & 15) * 4;
            cp_async16(dstBase + (r * PADB + w4) * 4, srcBase + r * 128 + w4);
        }
        CP_COMMIT();
    };

    issue_chunk(0);

    // load A tile (128 rows x 128 K) as tf32, k-permuted (overlaps chunk0 cp.async)
    for (int idx = tid; idx < 128 * 16; idx += 512) {
        int r  = idx >> 4;
        int c8 = (idx & 15) * 8;
        int grow = row0 + r;
        float4 v0, v1;
        if (grow < N_NODES) {
            v0 = *(const float4*)(A + grow * 128 + c8);
            v1 = *(const float4*)(A + grow * 128 + c8 + 4);
        } else {
            v0 = make_float4(0.f, 0.f, 0.f, 0.f);
            v1 = v0;
        }
        uint4 q0 = make_uint4(f2tf32(v0.x), f2tf32(v1.x), f2tf32(v0.y), f2tf32(v1.y));
        uint4 q1 = make_uint4(f2tf32(v0.z), f2tf32(v1.z), f2tf32(v0.w), f2tf32(v1.w));
        unsigned* p = sA + r * PADA + c8;
        *(uint4*)(p)     = q0;
        *(uint4*)(p + 4) = q1;
    }

    float acc[3][2][2][4];   // [mat][nt][row-frag][quad]

#pragma unroll
    for (int c = 0; c < 4; c++) {
        CP_WAIT0();
        __syncthreads();     // chunk c visible to all; all warps done reading buf[(c+1)&1]
        if (c < 3) issue_chunk(c + 1);

        if ((c & 1) == 0) {
#pragma unroll
            for (int m = 0; m < 3; m++)
#pragma unroll
                for (int n = 0; n < 2; n++)
#pragma unroll
                    for (int rf = 0; rf < 2; rf++)
#pragma unroll
                        for (int q = 0; q < 4; q++) acc[m][n][rf][q] = 0.f;
        }

        const unsigned* bufc = (c & 1) ? sB1 : sB0;
        int kb = (c & 1) * 64;
        const unsigned* aW = sA + (wr * 32 + g) * PADA + kb + 2 * tg;
        const unsigned* bW = bufc + (wc * 16 + g) * PADB + 2 * tg;

#pragma unroll
        for (int ks = 0; ks < 8; ks++) {
            int k0 = ks * 8;
            uint2 a0Lo = *(const uint2*)(aW + k0);
            uint2 a0Hi = *(const uint2*)(aW + 8 * PADA + k0);
            uint2 a1Lo = *(const uint2*)(aW + 16 * PADA + k0);
            uint2 a1Hi = *(const uint2*)(aW + 24 * PADA + k0);
#pragma unroll
            for (int mat = 0; mat < 3; mat++) {
#pragma unroll
                for (int nt = 0; nt < 2; nt++) {
                    uint2 b = *(const uint2*)(bW + (mat * 64 + nt * 8) * PADB + k0);
                    mma_tf32(acc[mat][nt][0], a0Lo.x, a0Hi.x, a0Lo.y, a0Hi.y, b.x, b.y);
                    mma_tf32(acc[mat][nt][1], a1Lo.x, a1Hi.x, a1Lo.y, a1Hi.y, b.x, b.y);
                }
            }
        }

        if (c & 1) {
            int j = c >> 1;
            // epilogue: msg = relu(gamma*m + beta) -> fp16
#pragma unroll
            for (int rf = 0; rf < 2; rf++) {
                int ra = row0 + wr * 32 + rf * 16 + g;
                int rb = ra + 8;
#pragma unroll
                for (int nt = 0; nt < 2; nt++) {
                    int col = 64 * j + wc * 16 + nt * 8 + 2 * tg;
                    const float* m_  = acc[0][nt][rf];
                    const float* ga_ = acc[1][nt][rf];
                    const float* be_ = acc[2][nt][rf];
                    float v0 = fmaxf(fmaf(ga_[0], m_[0], be_[0]), 0.f);
                    float v1 = fmaxf(fmaf(ga_[1], m_[1], be_[1]), 0.f);
                    float v2 = fmaxf(fmaf(ga_[2], m_[2], be_[2]), 0.f);
                    float v3 = fmaxf(fmaf(ga_[3], m_[3], be_[3]), 0.f);
                    __half2 ha = __floats2half2_rn(v0, v1);
                    __half2 hb = __floats2half2_rn(v2, v3);
                    if (ra < N_NODES) g_msg[ra * 64 + (col >> 1)] = ha;
                    if (rb < N_NODES) g_msg[rb * 64 + (col >> 1)] = hb;
                }
            }
        }
    }
}

// ==================== output head: sigmoid(g_h @ Wp.T + bp) ====================

__global__ void gemm_out_tc(const float* __restrict__ bp,
                            float* __restrict__ out) {
    extern __shared__ unsigned smem[];
    unsigned* sA = smem;                 // 64*PADA
    unsigned* sB = smem + 64 * PADA;     // 64*PADA

    int tid  = threadIdx.x;
    int wid  = tid >> 5;
    int lane = tid & 31;
    int g    = lane >> 2;
    int tg   = lane & 3;
    int wr   = wid >> 1;
    int wc   = wid & 1;
    int row0 = blockIdx.x * 64;

    for (int idx = tid; idx < 64 * 32; idx += 256) {
        int r = idx >> 5;
        int c4 = (idx & 31) * 4;
        int grow = row0 + r;
        float4 v = (grow < N_NODES) ? *(const float4*)(g_h + grow * 128 + c4)
                                    : make_float4(0.f, 0.f, 0.f, 0.f);
        unsigned* p = sA + r * PADA + c4;
        p[0] = f2tf32(v.x); p[1] = f2tf32(v.y); p[2] = f2tf32(v.z); p[3] = f2tf32(v.w);
    }
    for (int idx = tid; idx < 64 * 32; idx += 256) {
        int r = idx >> 5;
        int c4 = (idx & 31) * 4;
        uint4 v = *(const uint4*)(g_Bp + r * 128 + c4);
        *(uint4*)(sB + r * PADA + c4) = v;
    }
    __syncthreads();

    float acc[4][4];
#pragma unroll
    for (int n = 0; n < 4; n++)
#pragma unroll
        for (int q = 0; q < 4; q++) acc[n][q] = 0.f;

    const unsigned* aW = sA + (wr * 16 + g) * PADA + tg;
#pragma unroll
    for (int ks = 0; ks < 16; ks++) {
        int k0 = ks * 8;
        unsigned a0 = aW[k0];
        unsigned a1 = aW[8 * PADA + k0];
        unsigned a2 = aW[k0 + 4];
        unsigned a3 = aW[8 * PADA + k0 + 4];
#pragma unroll
        for (int nt = 0; nt < 4; nt++) {
            const unsigned* bptr = sB + (wc * 32 + nt * 8 + g) * PADA + k0 + tg;
            mma_tf32(acc[nt], a0, a1, a2, a3, bptr[0], bptr[4]);
        }
    }

    int ra = row0 + wr * 16 + g;
    int rb = ra + 8;
#pragma unroll
    for (int nt = 0; nt < 4; nt++) {
        int col = wc * 32 + nt * 8 + 2 * tg;
        float bpv0 = bp[col], bpv1 = bp[col + 1];
        float v0 = 1.f / (1.f + __expf(-(acc[nt][0] + bpv0)));
        float v1 = 1.f / (1.f + __expf(-(acc[nt][1] + bpv1)));
        float v2 = 1.f / (1.f + __expf(-(acc[nt][2] + bpv0)));
        float v3 = 1.f / (1.f + __expf(-(acc[nt][3] + bpv1)));
        if (ra < N_NODES) *(float2*)&out[ra * 64 + col] = make_float2(v0, v1);
        if (rb < N_NODES) *(float2*)&out[rb * 64 + col] = make_float2(v2, v3);
    }
}

// ==================== aggregate + layernorm (fused, warp per node, fp16 gather) ========

__global__ void aggregate_ln_kernel(const float* __restrict__ gam,
                                    const float* __restrict__ bet) {
    int gw = (blockIdx.x * blockDim.x + threadIdx.x) >> 5;
    int lane = threadIdx.x & 31;
    if (gw >= N_NODES) return;

    int s0 = g_off[gw], s1 = s0 + g_deg[gw];
    const uint2* msg2 = (const uint2*)g_msg;   // 32 uint2 (= 4 halves each) per node row

    float4 acc0 = make_float4(0.f, 0.f, 0.f, 0.f);
    float4 acc1 = make_float4(0.f, 0.f, 0.f, 0.f);
    float4 acc2 = make_float4(0.f, 0.f, 0.f, 0.f);
    float4 acc3 = make_float4(0.f, 0.f, 0.f, 0.f);
    int i = s0;
    for (; i + 4 <= s1; i += 4) {
        int sa = __ldg(&g_csr_src[i]);
        int sb = __ldg(&g_csr_src[i + 1]);
        int sc = __ldg(&g_csr_src[i + 2]);
        int sd = __ldg(&g_csr_src[i + 3]);
        uint2 ua = __ldg(&msg2[sa * 32 + lane]);
        uint2 ub = __ldg(&msg2[sb * 32 + lane]);
        uint2 uc = __ldg(&msg2[sc * 32 + lane]);
        uint2 ud = __ldg(&msg2[sd * 32 + lane]);
        float2 a01 = __half22float2(*(__half2*)&ua.x), a23 = __half22float2(*(__half2*)&ua.y);
        float2 b01 = __half22float2(*(__half2*)&ub.x), b23 = __half22float2(*(__half2*)&ub.y);
        float2 c01 = __half22float2(*(__half2*)&uc.x), c23 = __half22float2(*(__half2*)&uc.y);
        float2 d01 = __half22float2(*(__half2*)&ud.x), d23 = __half22float2(*(__half2*)&ud.y);
        acc0.x += a01.x; acc0.y += a01.y; acc0.z += a23.x; acc0.w += a23.y;
        acc1.x += b01.x; acc1.y += b01.y; acc1.z += b23.x; acc1.w += b23.y;
        acc2.x += c01.x; acc2.y += c01.y; acc2.z += c23.x; acc2.w += c23.y;
        acc3.x += d01.x; acc3.y += d01.y; acc3.z += d23.x; acc3.w += d23.y;
    }
    for (; i < s1; i++) {
        int sa = __ldg(&g_csr_src[i]);
        uint2 ua = __ldg(&msg2[sa * 32 + lane]);
        float2 a01 = __half22float2(*(__half2*)&ua.x), a23 = __half22float2(*(__half2*)&ua.y);
        acc0.x += a01.x; acc0.y += a01.y; acc0.z += a23.x; acc0.w += a23.y;
    }
    float4 acc = make_float4(acc0.x + acc1.x + acc2.x + acc3.x,
                             acc0.y + acc1.y + acc2.y + acc3.y,
                             acc0.z + acc1.z + acc2.z + acc3.z,
                             acc0.w + acc1.w + acc2.w + acc3.w);

    float sum = acc.x + acc.y + acc.z + acc.w;
    float sq  = acc.x * acc.x + acc.y * acc.y + acc.z * acc.z + acc.w * acc.w;
#pragma unroll
    for (int o = 16; o > 0; o >>= 1) {
        sum += __shfl_xor_sync(0xffffffffu, sum, o);
        sq  += __shfl_xor_sync(0xffffffffu, sq,  o);
    }
    float mu  = sum * (1.f / 128.f);
    float var = sq * (1.f / 128.f) - mu * mu;
    float rs  = rsqrtf(var + 1e-5f);

    float4 gv = *(const float4*)&gam[lane * 4];
    float4 bv = *(const float4*)&bet[lane * 4];
    float4 o;
    o.x = (acc.x - mu) * rs * gv.x + bv.x;
    o.y = (acc.y - mu) * rs * gv.y + bv.y;
    o.z = (acc.z - mu) * rs * gv.z + bv.z;
    o.w = (acc.w - mu) * rs * gv.w + bv.w;
    *(float4*)&g_h[gw * 128 + lane * 4] = o;
}

// ============================ launch ============================

extern "C" void kernel_launch(void* const* d_in, const int* in_sizes, int n_in,
                              void* d_out, int out_size) {
    const float* features = (const float*)d_in[0];
    const int*   src      = (const int*)  d_in[1];
    const int*   dst      = (const int*)  d_in[2];
    const float* W1       = (const float*)d_in[3];
    const float* F1       = (const float*)d_in[4];
    const float* g1       = (const float*)d_in[5];
    const float* b1       = (const float*)d_in[6];
    const float* W2       = (const float*)d_in[7];
    const float* F2       = (const float*)d_in[8];
    const float* g2       = (const float*)d_in[9];
    const float* b2       = (const float*)d_in[10];
    const float* Wp       = (const float*)d_in[11];
    const float* bp       = (const float*)d_in[12];
    float* out = (float*)d_out;

    // persistent side stream + events (host resources, created once)
    static cudaStream_t s_side = nullptr;
    static cudaEvent_t  ev_fork = nullptr, ev_join = nullptr, ev_join2 = nullptr;
    if (s_side == nullptr) {
        cudaStreamCreateWithFlags(&s_side, cudaStreamNonBlocking);
        cudaEventCreateWithFlags(&ev_fork,  cudaEventDisableTiming);
        cudaEventCreateWithFlags(&ev_join,  cudaEventDisableTiming);
        cudaEventCreateWithFlags(&ev_join2, cudaEventDisableTiming);
    }

    const int smem_film = (128 * PADA + 2 * 192 * PADB) * 4;   // 180224 B
    const int smem_out  = (64 * PADA + 64 * PADA) * 4;         // 69632 B
    cudaFuncSetAttribute(film_gemm_fused, cudaFuncAttributeMaxDynamicSharedMemorySize, smem_film);
    cudaFuncSetAttribute(gemm_out_tc,     cudaFuncAttributeMaxDynamicSharedMemorySize, smem_out);

    dim3 film_grid((N_NODES + 127) / 128);
    dim3 agg_grid((N_NODES + 7) / 8);

    // fork side branch off the capture-origin stream
    cudaEventRecord(ev_fork, 0);
    cudaStreamWaitEvent(s_side, ev_fork, 0);

    // branch B (side stream): CSR build -> ev_join; then layer-2/head prep -> ev_join2
    zero_deg_kernel<<<(N_NODES + 255) / 256, 256, 0, s_side>>>();
    hist_kernel<<<(N_EDGES + 255) / 256, 256, 0, s_side>>>(dst);
    offsets_kernel<<<(N_NODES + 255) / 256, 256, 0, s_side>>>();
    fill_csr_kernel<<<(N_EDGES + 255) / 256, 256, 0, s_side>>>(src, dst);
    cudaEventRecord(ev_join, s_side);
    prep_weights<<<(2 * 192 * 32 + 255) / 256, 256, 0, s_side>>>(W2, F2, 1);
    prep_wp<<<(64 * 32 + 255) / 256, 256, 0, s_side>>>(Wp);
    cudaEventRecord(ev_join2, s_side);

    // branch A (origin stream): layer-1 prep + GEMM
    prep_weights<<<(2 * 192 * 32 + 255) / 256, 256>>>(W1, F1, 0);
    film_gemm_fused<<<film_grid, 512, smem_film>>>(features, 0);

    // join: aggregation needs CSR + msg
    cudaStreamWaitEvent(0, ev_join, 0);
    aggregate_ln_kernel<<<agg_grid, 256>>>(g1, b1);

    // layer 2 (needs g_Bt2 from side stream)
    cudaStreamWaitEvent(0, ev_join2, 0);
    film_gemm_fused<<<film_grid, 512, smem_film>>>(nullptr, 1);
    aggregate_ln_kernel<<<agg_grid, 256>>>(g2, b2);

    // output head
    gemm_out_tc<<<(N_NODES + 63) / 64, 256, smem_out>>>(bp, out);
}

// round 10
// speedup vs baseline: 1.2103x; 1.2103x over previous
#include <cuda_runtime.h>
#include <cuda_fp16.h>

#define N_NODES 50000
#define N_EDGES 600000
#define DIM 128
#define OUTD 64

#define PADA 136   // fp32/tf32 rows (head kernel); mod 32 = 8 -> conflict-free
#define PADH 72    // fp16 rows: 64 data words (128 halves) + 8 pad; mod 32 = 8 -> conflict-free

// ---- scratch (static device globals; no runtime allocation) ----
__device__ __half2   g_msg[N_NODES * 64];   // fp16 messages (128 per node)
__device__ float     g_h[N_NODES * DIM];
__device__ int       g_deg[N_NODES];
__device__ int       g_off[N_NODES];
__device__ int       g_cur[N_NODES];
__device__ int       g_ctr;
__device__ int       g_csr_src[N_EDGES];
// fp16 weight panels, k-permuted, usage order: row p = mat*128 + c;
// mat0: W[c] (m), mat1: F[c] (gamma), mat2: F[128+c] (beta). 64 half2-words per row.
__device__ __align__(16) __half2 g_BtH1[384 * 64];
__device__ __align__(16) __half2 g_BtH2[384 * 64];
__device__ unsigned  g_Bp[64 * 128];        // Wp, tf32 (head)

// ============================ helpers ============================

__device__ __forceinline__ unsigned f2tf32(float f) {
    unsigned u;
    asm("cvt.rna.tf32.f32 %0, %1;" : "=r"(u) : "f"(f));
    return u;
}

__device__ __forceinline__ unsigned h2u(__half2 h) {
    return *(unsigned*)&h;
}

__device__ __forceinline__ void mma_tf32(float* c,
                                         unsigned a0, unsigned a1, unsigned a2, unsigned a3,
                                         unsigned b0, unsigned b1) {
    asm volatile(
        "mma.sync.aligned.m16n8k8.row.col.f32.tf32.tf32.f32 "
        "{%0,%1,%2,%3}, {%4,%5,%6,%7}, {%8,%9}, {%0,%1,%2,%3};"
        : "+f"(c[0]), "+f"(c[1]), "+f"(c[2]), "+f"(c[3])
        : "r"(a0), "r"(a1), "r"(a2), "r"(a3), "r"(b0), "r"(b1));
}

__device__ __forceinline__ void mma_f16(float* c,
                                        unsigned a0, unsigned a1, unsigned a2, unsigned a3,
                                        unsigned b0, unsigned b1) {
    asm volatile(
        "mma.sync.aligned.m16n8k16.row.col.f32.f16.f16.f32 "
        "{%0,%1,%2,%3}, {%4,%5,%6,%7}, {%8,%9}, {%0,%1,%2,%3};"
        : "+f"(c[0]), "+f"(c[1]), "+f"(c[2]), "+f"(c[3])
        : "r"(a0), "r"(a1), "r"(a2), "r"(a3), "r"(b0), "r"(b1));
}

__device__ __forceinline__ void cp_async16(unsigned smem_addr, const void* gptr) {
    asm volatile("cp.async.cg.shared.global [%0], [%1], 16;"
                 :: "r"(smem_addr), "l"(gptr));
}
#define CP_COMMIT() asm volatile("cp.async.commit_group;" ::: "memory")
#define CP_WAIT0()  asm volatile("cp.async.wait_group 0;" ::: "memory")

// ============================ CSR build ============================

__global__ void zero_deg_kernel() {
    int i = blockIdx.x * blockDim.x + threadIdx.x;
    if (i < N_NODES) g_deg[i] = 0;
    if (i == 0) g_ctr = 0;
}

__global__ void hist_kernel(const int* __restrict__ dst) {
    int e = blockIdx.x * blockDim.x + threadIdx.x;
    if (e < N_EDGES) atomicAdd(&g_deg[dst[e]], 1);
}

// unordered disjoint range claim (aggregation is order-agnostic)
__global__ void offsets_kernel() {
    int i = blockIdx.x * blockDim.x + threadIdx.x;
    if (i < N_NODES) {
        int d = g_deg[i];
        int s = atomicAdd(&g_ctr, d);
        g_off[i] = s;
        g_cur[i] = s;
    }
}

__global__ void fill_csr_kernel(const int* __restrict__ src, const int* __restrict__ dst) {
    int e = blockIdx.x * blockDim.x + threadIdx.x;
    if (e < N_EDGES) {
        int d = dst[e];
        int p = atomicAdd(&g_cur[d], 1);
        g_csr_src[p] = src[e];
    }
}

// ==================== weight prep (fp32 -> fp16, k-permuted 16-groups) ====================
// Within each 16-k group: word 2t = (k2t, k2t+1), word 2t+1 = (k2t+8, k2t+9),
// so a thread's m16n8k16 operand pair (b0,b1) is one contiguous uint2.

__global__ void prep_weights(const float* __restrict__ W,
                             const float* __restrict__ F,
                             int layer) {
    __half2* dst = layer ? g_BtH2 : g_BtH1;
    int idx = blockIdx.x * blockDim.x + threadIdx.x;   // over 384 rows x 8 kgroups
    if (idx >= 384 * 8) return;
    int p  = idx >> 3;
    int kg = idx & 7;
    int mat = p >> 7, c = p & 127;
    const float* srcRow = (mat == 0) ? W + c * 128
                        : (mat == 1) ? F + c * 128
                                     : F + (128 + c) * 128;
    const float* s = srcRow + kg * 16;
    float4 f0 = *(const float4*)(s);
    float4 f1 = *(const float4*)(s + 4);
    float4 f2 = *(const float4*)(s + 8);
    float4 f3 = *(const float4*)(s + 12);
    uint4 q0 = make_uint4(h2u(__floats2half2_rn(f0.x, f0.y)),   // k0,k1
                          h2u(__floats2half2_rn(f2.x, f2.y)),   // k8,k9
                          h2u(__floats2half2_rn(f0.z, f0.w)),   // k2,k3
                          h2u(__floats2half2_rn(f2.z, f2.w)));  // k10,k11
    uint4 q1 = make_uint4(h2u(__floats2half2_rn(f1.x, f1.y)),   // k4,k5
                          h2u(__floats2half2_rn(f3.x, f3.y)),   // k12,k13
                          h2u(__floats2half2_rn(f1.z, f1.w)),   // k6,k7
                          h2u(__floats2half2_rn(f3.z, f3.w)));  // k14,k15
    uint4* d = (uint4*)(dst + p * 64 + kg * 8);
    d[0] = q0;
    d[1] = q1;
}

__global__ void prep_wp(const float* __restrict__ Wp) {
    int idx = blockIdx.x * blockDim.x + threadIdx.x;   // over 64*32 float4 groups
    if (idx >= 64 * 32) return;
    float4 v = *(const float4*)(Wp + idx * 4);
    unsigned* p = g_Bp + idx * 4;
    p[0] = f2tf32(v.x); p[1] = f2tf32(v.y); p[2] = f2tf32(v.z); p[3] = f2tf32(v.w);
}

// ==================== fused FiLM GEMM (fp16 m16n8k16, M=128, 512 thr) ====================
// Full 384-row weight panel resident in smem (one cp.async burst, one barrier).
// 16 warps: wr = wid>>2 owns rows [wr*32,+32); wc = wid&3 owns cols [wc*16,+16) of each
// mat for each j half. Per k16-step: 4 A + 6 B LDS.64 -> 12 m16n8k16 MMAs.

__global__ void film_gemm_fused(const float* __restrict__ Ain, int layer) {
    extern __shared__ unsigned smem[];
    unsigned* sA = smem;                   // 128*PADH (fp16, k-permuted)
    unsigned* sB = smem + 128 * PADH;      // 384*PADH (full weight panel)

    const float*   A  = layer ? g_h : Ain;
    const __half2* Bt = layer ? g_BtH2 : g_BtH1;

    int tid  = threadIdx.x;     // 512
    int wid  = tid >> 5;
    int lane = tid & 31;
    int g    = lane >> 2;       // 0..7
    int tg   = lane & 3;        // 0..3
    int wr   = wid >> 2;        // 0..3 (32-row group)
    int wc   = wid & 3;         // 0..3 (16-col group per mat per j)
    int row0 = blockIdx.x * 128;

    // stream the full weight panel: 384 rows x 16 uint4 = 6144 cp.async
    unsigned sBu = (unsigned)__cvta_generic_to_shared(sB);
#pragma unroll
    for (int t = 0; t < 12; t++) {
        int idx = tid + t * 512;
        int r  = idx >> 4;
        int w4 = (idx & 15) * 4;
        cp_async16(sBu + (r * PADH + w4) * 4, Bt + r * 64 + w4);
    }
    CP_COMMIT();

    // convert A tile (128 rows x 128 K) fp32 -> fp16, k-permuted (overlaps cp.async)
    for (int idx = tid; idx < 128 * 8; idx += 512) {
        int r  = idx >> 3;
        int kg = idx & 7;
        int grow = row0 + r;
        float4 f0, f1, f2, f3;
        if (grow < N_NODES) {
            const float* s = A + grow * 128 + kg * 16;
            f0 = *(const float4*)(s);
            f1 = *(const float4*)(s + 4);
            f2 = *(const float4*)(s + 8);
            f3 = *(const float4*)(s + 12);
        } else {
            f0 = make_float4(0.f, 0.f, 0.f, 0.f);
            f1 = f0; f2 = f0; f3 = f0;
        }
        uint4 q0 = make_uint4(h2u(__floats2half2_rn(f0.x, f0.y)),
                              h2u(__floats2half2_rn(f2.x, f2.y)),
                              h2u(__floats2half2_rn(f0.z, f0.w)),
                              h2u(__floats2half2_rn(f2.z, f2.w)));
        uint4 q1 = make_uint4(h2u(__floats2half2_rn(f1.x, f1.y)),
                              h2u(__floats2half2_rn(f3.x, f3.y)),
                              h2u(__floats2half2_rn(f1.z, f1.w)),
                              h2u(__floats2half2_rn(f3.z, f3.w)));
        unsigned* p = sA + r * PADH + kg * 8;
        *(uint4*)(p)     = q0;
        *(uint4*)(p + 4) = q1;
    }

    CP_WAIT0();
    __syncthreads();

    const unsigned* aW = sA + (wr * 32 + g) * PADH + 2 * tg;

#pragma unroll
    for (int j = 0; j < 2; j++) {
        float acc[3][2][2][4];   // [mat][nt][row-frag][quad]
#pragma unroll
        for (int m = 0; m < 3; m++)
#pragma unroll
            for (int n = 0; n < 2; n++)
#pragma unroll
                for (int rf = 0; rf < 2; rf++)
#pragma unroll
                    for (int q = 0; q < 4; q++) acc[m][n][rf][q] = 0.f;

        const unsigned* bW = sB + (j * 64 + wc * 16 + g) * PADH + 2 * tg;

#pragma unroll
        for (int ks = 0; ks < 8; ks++) {
            int k0 = ks * 8;
            uint2 a0 = *(const uint2*)(aW + k0);               // rows wr*32+g:   (a0,a2)
            uint2 a0h = *(const uint2*)(aW + 8 * PADH + k0);   // +8:             (a1,a3)
            uint2 a1 = *(const uint2*)(aW + 16 * PADH + k0);   // +16
            uint2 a1h = *(const uint2*)(aW + 24 * PADH + k0);  // +24
#pragma unroll
            for (int mat = 0; mat < 3; mat++) {
#pragma unroll
                for (int nt = 0; nt < 2; nt++) {
                    uint2 b = *(const uint2*)(bW + (mat * 128 + nt * 8) * PADH + k0);
                    mma_f16(acc[mat][nt][0], a0.x, a0h.x, a0.y, a0h.y, b.x, b.y);
                    mma_f16(acc[mat][nt][1], a1.x, a1h.x, a1.y, a1h.y, b.x, b.y);
                }
            }
        }

        // epilogue: msg = relu(gamma*m + beta) -> fp16
#pragma unroll
        for (int rf = 0; rf < 2; rf++) {
            int ra = row0 + wr * 32 + rf * 16 + g;
            int rb = ra + 8;
#pragma unroll
            for (int nt = 0; nt < 2; nt++) {
                int col = 64 * j + wc * 16 + nt * 8 + 2 * tg;
                const float* m_  = acc[0][nt][rf];
                const float* ga_ = acc[1][nt][rf];
                const float* be_ = acc[2][nt][rf];
                float v0 = fmaxf(fmaf(ga_[0], m_[0], be_[0]), 0.f);
                float v1 = fmaxf(fmaf(ga_[1], m_[1], be_[1]), 0.f);
                float v2 = fmaxf(fmaf(ga_[2], m_[2], be_[2]), 0.f);
                float v3 = fmaxf(fmaf(ga_[3], m_[3], be_[3]), 0.f);
                __half2 ha = __floats2half2_rn(v0, v1);
                __half2 hb = __floats2half2_rn(v2, v3);
                if (ra < N_NODES) g_msg[ra * 64 + (col >> 1)] = ha;
                if (rb < N_NODES) g_msg[rb * 64 + (col >> 1)] = hb;
            }
        }
    }
}

// ==================== output head: sigmoid(g_h @ Wp.T + bp) ====================

__global__ void gemm_out_tc(const float* __restrict__ bp,
                            float* __restrict__ out) {
    extern __shared__ unsigned smem[];
    unsigned* sA = smem;                 // 64*PADA
    unsigned* sB = smem + 64 * PADA;     // 64*PADA

    int tid  = threadIdx.x;
    int wid  = tid >> 5;
    int lane = tid & 31;
    int g    = lane >> 2;
    int tg   = lane & 3;
    int wr   = wid >> 1;
    int wc   = wid & 1;
    int row0 = blockIdx.x * 64;

    for (int idx = tid; idx < 64 * 32; idx += 256) {
        int r = idx >> 5;
        int c4 = (idx & 31) * 4;
        int grow = row0 + r;
        float4 v = (grow < N_NODES) ? *(const float4*)(g_h + grow * 128 + c4)
                                    : make_float4(0.f, 0.f, 0.f, 0.f);
        unsigned* p = sA + r * PADA + c4;
        p[0] = f2tf32(v.x); p[1] = f2tf32(v.y); p[2] = f2tf32(v.z); p[3] = f2tf32(v.w);
    }
    for (int idx = tid; idx < 64 * 32; idx += 256) {
        int r = idx >> 5;
        int c4 = (idx & 31) * 4;
        uint4 v = *(const uint4*)(g_Bp + r * 128 + c4);
        *(uint4*)(sB + r * PADA + c4) = v;
    }
    __syncthreads();

    float acc[4][4];
#pragma unroll
    for (int n = 0; n < 4; n++)
#pragma unroll
        for (int q = 0; q < 4; q++) acc[n][q] = 0.f;

    const unsigned* aW = sA + (wr * 16 + g) * PADA + tg;
#pragma unroll
    for (int ks = 0; ks < 16; ks++) {
        int k0 = ks * 8;
        unsigned a0 = aW[k0];
        unsigned a1 = aW[8 * PADA + k0];
        unsigned a2 = aW[k0 + 4];
        unsigned a3 = aW[8 * PADA + k0 + 4];
#pragma unroll
        for (int nt = 0; nt < 4; nt++) {
            const unsigned* bptr = sB + (wc * 32 + nt * 8 + g) * PADA + k0 + tg;
            mma_tf32(acc[nt], a0, a1, a2, a3, bptr[0], bptr[4]);
        }
    }

    int ra = row0 + wr * 16 + g;
    int rb = ra + 8;
#pragma unroll
    for (int nt = 0; nt < 4; nt++) {
        int col = wc * 32 + nt * 8 + 2 * tg;
        float bpv0 = bp[col], bpv1 = bp[col + 1];
        float v0 = 1.f / (1.f + __expf(-(acc[nt][0] + bpv0)));
        float v1 = 1.f / (1.f + __expf(-(acc[nt][1] + bpv1)));
        float v2 = 1.f / (1.f + __expf(-(acc[nt][2] + bpv0)));
        float v3 = 1.f / (1.f + __expf(-(acc[nt][3] + bpv1)));
        if (ra < N_NODES) *(float2*)&out[ra * 64 + col] = make_float2(v0, v1);
        if (rb < N_NODES) *(float2*)&out[rb * 64 + col] = make_float2(v2, v3);
    }
}

// ==================== aggregate + layernorm (fused, warp per node, fp16 gather) ========

__global__ void aggregate_ln_kernel(const float* __restrict__ gam,
                                    const float* __restrict__ bet) {
    int gw = (blockIdx.x * blockDim.x + threadIdx.x) >> 5;
    int lane = threadIdx.x & 31;
    if (gw >= N_NODES) return;

    int s0 = g_off[gw], s1 = s0 + g_deg[gw];
    const uint2* msg2 = (const uint2*)g_msg;   // 32 uint2 (= 4 halves each) per node row

    float4 acc0 = make_float4(0.f, 0.f, 0.f, 0.f);
    float4 acc1 = make_float4(0.f, 0.f, 0.f, 0.f);
    float4 acc2 = make_float4(0.f, 0.f, 0.f, 0.f);
    float4 acc3 = make_float4(0.f, 0.f, 0.f, 0.f);
    int i = s0;
    for (; i + 4 <= s1; i += 4) {
        int sa = __ldg(&g_csr_src[i]);
        int sb = __ldg(&g_csr_src[i + 1]);
        int sc = __ldg(&g_csr_src[i + 2]);
        int sd = __ldg(&g_csr_src[i + 3]);
        uint2 ua = __ldg(&msg2[sa * 32 + lane]);
        uint2 ub = __ldg(&msg2[sb * 32 + lane]);
        uint2 uc = __ldg(&msg2[sc * 32 + lane]);
        uint2 ud = __ldg(&msg2[sd * 32 + lane]);
        float2 a01 = __half22float2(*(__half2*)&ua.x), a23 = __half22float2(*(__half2*)&ua.y);
        float2 b01 = __half22float2(*(__half2*)&ub.x), b23 = __half22float2(*(__half2*)&ub.y);
        float2 c01 = __half22float2(*(__half2*)&uc.x), c23 = __half22float2(*(__half2*)&uc.y);
        float2 d01 = __half22float2(*(__half2*)&ud.x), d23 = __half22float2(*(__half2*)&ud.y);
        acc0.x += a01.x; acc0.y += a01.y; acc0.z += a23.x; acc0.w += a23.y;
        acc1.x += b01.x; acc1.y += b01.y; acc1.z += b23.x; acc1.w += b23.y;
        acc2.x += c01.x; acc2.y += c01.y; acc2.z += c23.x; acc2.w += c23.y;
        acc3.x += d01.x; acc3.y += d01.y; acc3.z += d23.x; acc3.w += d23.y;
    }
    for (; i < s1; i++) {
        int sa = __ldg(&g_csr_src[i]);
        uint2 ua = __ldg(&msg2[sa * 32 + lane]);
        float2 a01 = __half22float2(*(__half2*)&ua.x), a23 = __half22float2(*(__half2*)&ua.y);
        acc0.x += a01.x; acc0.y += a01.y; acc0.z += a23.x; acc0.w += a23.y;
    }
    float4 acc = make_float4(acc0.x + acc1.x + acc2.x + acc3.x,
                             acc0.y + acc1.y + acc2.y + acc3.y,
                             acc0.z + acc1.z + acc2.z + acc3.z,
                             acc0.w + acc1.w + acc2.w + acc3.w);

    float sum = acc.x + acc.y + acc.z + acc.w;
    float sq  = acc.x * acc.x + acc.y * acc.y + acc.z * acc.z + acc.w * acc.w;
#pragma unroll
    for (int o = 16; o > 0; o >>= 1) {
        sum += __shfl_xor_sync(0xffffffffu, sum, o);
        sq  += __shfl_xor_sync(0xffffffffu, sq,  o);
    }
    float mu  = sum * (1.f / 128.f);
    float var = sq * (1.f / 128.f) - mu * mu;
    float rs  = rsqrtf(var + 1e-5f);

    float4 gv = *(const float4*)&gam[lane * 4];
    float4 bv = *(const float4*)&bet[lane * 4];
    float4 o;
    o.x = (acc.x - mu) * rs * gv.x + bv.x;
    o.y = (acc.y - mu) * rs * gv.y + bv.y;
    o.z = (acc.z - mu) * rs * gv.z + bv.z;
    o.w = (acc.w - mu) * rs * gv.w + bv.w;
    *(float4*)&g_h[gw * 128 + lane * 4] = o;
}

// ============================ launch ============================

extern "C" void kernel_launch(void* const* d_in, const int* in_sizes, int n_in,
                              void* d_out, int out_size) {
    const float* features = (const float*)d_in[0];
    const int*   src      = (const int*)  d_in[1];
    const int*   dst      = (const int*)  d_in[2];
    const float* W1       = (const float*)d_in[3];
    const float* F1       = (const float*)d_in[4];
    const float* g1       = (const float*)d_in[5];
    const float* b1       = (const float*)d_in[6];
    const float* W2       = (const float*)d_in[7];
    const float* F2       = (const float*)d_in[8];
    const float* g2       = (const float*)d_in[9];
    const float* b2       = (const float*)d_in[10];
    const float* Wp       = (const float*)d_in[11];
    const float* bp       = (const float*)d_in[12];
    float* out = (float*)d_out;

    // persistent side stream + events (host resources, created once)
    static cudaStream_t s_side = nullptr;
    static cudaEvent_t  ev_fork = nullptr, ev_join = nullptr, ev_join2 = nullptr;
    if (s_side == nullptr) {
        cudaStreamCreateWithFlags(&s_side, cudaStreamNonBlocking);
        cudaEventCreateWithFlags(&ev_fork,  cudaEventDisableTiming);
        cudaEventCreateWithFlags(&ev_join,  cudaEventDisableTiming);
        cudaEventCreateWithFlags(&ev_join2, cudaEventDisableTiming);
    }

    const int smem_film = (128 * PADH + 384 * PADH) * 4;   // 147456 B
    const int smem_out  = (64 * PADA + 64 * PADA) * 4;     // 69632 B
    cudaFuncSetAttribute(film_gemm_fused, cudaFuncAttributeMaxDynamicSharedMemorySize, smem_film);
    cudaFuncSetAttribute(gemm_out_tc,     cudaFuncAttributeMaxDynamicSharedMemorySize, smem_out);

    dim3 film_grid((N_NODES + 127) / 128);
    dim3 agg_grid((N_NODES + 7) / 8);

    // fork side branch off the capture-origin stream
    cudaEventRecord(ev_fork, 0);
    cudaStreamWaitEvent(s_side, ev_fork, 0);

    // branch B (side stream): CSR build -> ev_join; then layer-2/head prep -> ev_join2
    zero_deg_kernel<<<(N_NODES + 255) / 256, 256, 0, s_side>>>();
    hist_kernel<<<(N_EDGES + 255) / 256, 256, 0, s_side>>>(dst);
    offsets_kernel<<<(N_NODES + 255) / 256, 256, 0, s_side>>>();
    fill_csr_kernel<<<(N_EDGES + 255) / 256, 256, 0, s_side>>>(src, dst);
    cudaEventRecord(ev_join, s_side);
    prep_weights<<<(384 * 8 + 255) / 256, 256, 0, s_side>>>(W2, F2, 1);
    prep_wp<<<(64 * 32 + 255) / 256, 256, 0, s_side>>>(Wp);
    cudaEventRecord(ev_join2, s_side);

    // branch A (origin stream): layer-1 prep + GEMM
    prep_weights<<<(384 * 8 + 255) / 256, 256>>>(W1, F1, 0);
    film_gemm_fused<<<film_grid, 512, smem_film>>>(features, 0);

    // join: aggregation needs CSR + msg
    cudaStreamWaitEvent(0, ev_join, 0);
    aggregate_ln_kernel<<<agg_grid, 256>>>(g1, b1);

    // layer 2 (needs g_BtH2 from side stream)
    cudaStreamWaitEvent(0, ev_join2, 0);
    film_gemm_fused<<<film_grid, 512, smem_film>>>(nullptr, 1);
    aggregate_ln_kernel<<<agg_grid, 256>>>(g2, b2);

    // output head
    gemm_out_tc<<<(N_NODES + 63) / 64, 256, smem_out>>>(bp, out);
}

// round 11
// speedup vs baseline: 1.3762x; 1.1371x over previous
#include <cuda_runtime.h>
#include <cuda_fp16.h>

#define N_NODES 50000
#define N_EDGES 600000
#define NPAD    50048   // padded row count for raw tile copies
#define DIM 128
#define OUTD 64

#define PADH 72    // fp16 rows: 64 data words (128 halves) + 8 pad; mod 32 = 8 -> conflict-free

// ---- scratch (static device globals; no runtime allocation) ----
__device__ __half2   g_msg[N_NODES * 64];   // fp16 messages (128 per node)
__device__ __align__(16) __half2 g_hH[NPAD * 64];  // fp16 hidden state, k-permuted
__device__ int       g_deg[N_NODES];
__device__ int       g_off[N_NODES];
__device__ int       g_cur[N_NODES];
__device__ int       g_ctr;
__device__ int       g_csr_src[N_EDGES];
// fp16 weight panels, k-permuted, usage order: row p = mat*128 + c;
// mat0: W[c] (m), mat1: F[c] (gamma), mat2: F[128+c] (beta). 64 half2-words per row.
__device__ __align__(16) __half2 g_BtH1[384 * 64];
__device__ __align__(16) __half2 g_BtH2[384 * 64];
__device__ __align__(16) __half2 g_BpH[64 * 64];   // Wp fp16, k-permuted

// ============================ helpers ============================

__device__ __forceinline__ unsigned h2u(__half2 h) {
    return *(unsigned*)&h;
}

__device__ __forceinline__ void mma_f16(float* c,
                                        unsigned a0, unsigned a1, unsigned a2, unsigned a3,
                                        unsigned b0, unsigned b1) {
    asm volatile(
        "mma.sync.aligned.m16n8k16.row.col.f32.f16.f16.f32 "
        "{%0,%1,%2,%3}, {%4,%5,%6,%7}, {%8,%9}, {%0,%1,%2,%3};"
        : "+f"(c[0]), "+f"(c[1]), "+f"(c[2]), "+f"(c[3])
        : "r"(a0), "r"(a1), "r"(a2), "r"(a3), "r"(b0), "r"(b1));
}

__device__ __forceinline__ void cp_async16(unsigned smem_addr, const void* gptr) {
    asm volatile("cp.async.cg.shared.global [%0], [%1], 16;"
                 :: "r"(smem_addr), "l"(gptr));
}
#define CP_COMMIT() asm volatile("cp.async.commit_group;" ::: "memory")
#define CP_WAIT0()  asm volatile("cp.async.wait_group 0;" ::: "memory")

// ============================ CSR build ============================

__global__ void zero_deg_kernel() {
    int i = blockIdx.x * blockDim.x + threadIdx.x;
    if (i < N_NODES) g_deg[i] = 0;
    if (i == 0) g_ctr = 0;
}

__global__ void hist_kernel(const int* __restrict__ dst) {
    int e = blockIdx.x * blockDim.x + threadIdx.x;
    if (e < N_EDGES) atomicAdd(&g_deg[dst[e]], 1);
}

// unordered disjoint range claim (aggregation is order-agnostic)
__global__ void offsets_kernel() {
    int i = blockIdx.x * blockDim.x + threadIdx.x;
    if (i < N_NODES) {
        int d = g_deg[i];
        int s = atomicAdd(&g_ctr, d);
        g_off[i] = s;
        g_cur[i] = s;
    }
}

__global__ void fill_csr_kernel(const int* __restrict__ src, const int* __restrict__ dst) {
    int e = blockIdx.x * blockDim.x + threadIdx.x;
    if (e < N_EDGES) {
        int d = dst[e];
        int p = atomicAdd(&g_cur[d], 1);
        g_csr_src[p] = src[e];
    }
}

// ==================== weight prep (fp32 -> fp16, k-permuted 16-groups) ====================
// Within each 16-k group: slot(pair p) = p<4 ? 2p : 2(p-4)+1, i.e. words are
// (k0k1),(k8k9),(k2k3),(k10k11),(k4k5),(k12k13),(k6k7),(k14k15).

__global__ void prep_weights(const float* __restrict__ W,
                             const float* __restrict__ F,
                             int layer) {
    __half2* dst = layer ? g_BtH2 : g_BtH1;
    int idx = blockIdx.x * blockDim.x + threadIdx.x;   // over 384 rows x 8 kgroups
    if (idx >= 384 * 8) return;
    int p  = idx >> 3;
    int kg = idx & 7;
    int mat = p >> 7, c = p & 127;
    const float* srcRow = (mat == 0) ? W + c * 128
                        : (mat == 1) ? F + c * 128
                                     : F + (128 + c) * 128;
    const float* s = srcRow + kg * 16;
    float4 f0 = *(const float4*)(s);
    float4 f1 = *(const float4*)(s + 4);
    float4 f2 = *(const float4*)(s + 8);
    float4 f3 = *(const float4*)(s + 12);
    uint4 q0 = make_uint4(h2u(__floats2half2_rn(f0.x, f0.y)),
                          h2u(__floats2half2_rn(f2.x, f2.y)),
                          h2u(__floats2half2_rn(f0.z, f0.w)),
                          h2u(__floats2half2_rn(f2.z, f2.w)));
    uint4 q1 = make_uint4(h2u(__floats2half2_rn(f1.x, f1.y)),
                          h2u(__floats2half2_rn(f3.x, f3.y)),
                          h2u(__floats2half2_rn(f1.z, f1.w)),
                          h2u(__floats2half2_rn(f3.z, f3.w)));
    uint4* d = (uint4*)(dst + p * 64 + kg * 8);
    d[0] = q0;
    d[1] = q1;
}

__global__ void prep_wp(const float* __restrict__ Wp) {
    int idx = blockIdx.x * blockDim.x + threadIdx.x;   // over 64 rows x 8 kgroups
    if (idx >= 64 * 8) return;
    int p  = idx >> 3;
    int kg = idx & 7;
    const float* s = Wp + p * 128 + kg * 16;
    float4 f0 = *(const float4*)(s);
    float4 f1 = *(const float4*)(s + 4);
    float4 f2 = *(const float4*)(s + 8);
    float4 f3 = *(const float4*)(s + 12);
    uint4 q0 = make_uint4(h2u(__floats2half2_rn(f0.x, f0.y)),
                          h2u(__floats2half2_rn(f2.x, f2.y)),
                          h2u(__floats2half2_rn(f0.z, f0.w)),
                          h2u(__floats2half2_rn(f2.z, f2.w)));
    uint4 q1 = make_uint4(h2u(__floats2half2_rn(f1.x, f1.y)),
                          h2u(__floats2half2_rn(f3.x, f3.y)),
                          h2u(__floats2half2_rn(f1.z, f1.w)),
                          h2u(__floats2half2_rn(f3.z, f3.w)));
    uint4* d = (uint4*)(g_BpH + p * 64 + kg * 8);
    d[0] = q0;
    d[1] = q1;
}

// ==================== fused FiLM GEMM (fp16 m16n8k16, M=128, 512 thr) ====================
// Full 384-row weight panel resident in smem (one cp.async burst, one barrier).
// layer 0: A converted fp32->fp16 (features); layer 1: A raw-copied from fp16 g_hH.

__global__ void film_gemm_fused(const float* __restrict__ Ain, int layer) {
    extern __shared__ unsigned smem[];
    unsigned* sA = smem;                   // 128*PADH (fp16, k-permuted)
    unsigned* sB = smem + 128 * PADH;      // 384*PADH (full weight panel)

    const __half2* Bt = layer ? g_BtH2 : g_BtH1;

    int tid  = threadIdx.x;     // 512
    int wid  = tid >> 5;
    int lane = tid & 31;
    int g    = lane >> 2;       // 0..7
    int tg   = lane & 3;        // 0..3
    int wr   = wid >> 2;        // 0..3 (32-row group)
    int wc   = wid & 3;         // 0..3 (16-col group per mat per j)
    int row0 = blockIdx.x * 128;

    // stream the full weight panel: 384 rows x 16 uint4
    unsigned sBu = (unsigned)__cvta_generic_to_shared(sB);
#pragma unroll
    for (int t = 0; t < 12; t++) {
        int idx = tid + t * 512;
        int r  = idx >> 4;
        int w4 = (idx & 15) * 4;
        cp_async16(sBu + (r * PADH + w4) * 4, Bt + r * 64 + w4);
    }

    if (layer) {
        // A raw copy from fp16 permuted g_hH (padded to NPAD rows)
        unsigned sAu = (unsigned)__cvta_generic_to_shared(sA);
#pragma unroll
        for (int t = 0; t < 4; t++) {
            int idx = tid + t * 512;     // 128*16 = 2048
            int r  = idx >> 4;
            int w4 = (idx & 15) * 4;
            cp_async16(sAu + (r * PADH + w4) * 4, g_hH + (row0 + r) * 64 + w4);
        }
        CP_COMMIT();
    } else {
        CP_COMMIT();
        // convert A tile fp32 -> fp16, k-permuted (overlaps weight cp.async)
        for (int idx = tid; idx < 128 * 8; idx += 512) {
            int r  = idx >> 3;
            int kg = idx & 7;
            int grow = row0 + r;
            float4 f0, f1, f2, f3;
            if (grow < N_NODES) {
                const float* s = Ain + grow * 128 + kg * 16;
                f0 = *(const float4*)(s);
                f1 = *(const float4*)(s + 4);
                f2 = *(const float4*)(s + 8);
                f3 = *(const float4*)(s + 12);
            } else {
                f0 = make_float4(0.f, 0.f, 0.f, 0.f);
                f1 = f0; f2 = f0; f3 = f0;
            }
            uint4 q0 = make_uint4(h2u(__floats2half2_rn(f0.x, f0.y)),
                                  h2u(__floats2half2_rn(f2.x, f2.y)),
                                  h2u(__floats2half2_rn(f0.z, f0.w)),
                                  h2u(__floats2half2_rn(f2.z, f2.w)));
            uint4 q1 = make_uint4(h2u(__floats2half2_rn(f1.x, f1.y)),
                                  h2u(__floats2half2_rn(f3.x, f3.y)),
                                  h2u(__floats2half2_rn(f1.z, f1.w)),
                                  h2u(__floats2half2_rn(f3.z, f3.w)));
            unsigned* p = sA + r * PADH + kg * 8;
            *(uint4*)(p)     = q0;
            *(uint4*)(p + 4) = q1;
        }
    }

    CP_WAIT0();
    __syncthreads();

    const unsigned* aW = sA + (wr * 32 + g) * PADH + 2 * tg;

#pragma unroll
    for (int j = 0; j < 2; j++) {
        float acc[3][2][2][4];   // [mat][nt][row-frag][quad]
#pragma unroll
        for (int m = 0; m < 3; m++)
#pragma unroll
            for (int n = 0; n < 2; n++)
#pragma unroll
                for (int rf = 0; rf < 2; rf++)
#pragma unroll
                    for (int q = 0; q < 4; q++) acc[m][n][rf][q] = 0.f;

        const unsigned* bW = sB + (j * 64 + wc * 16 + g) * PADH + 2 * tg;

#pragma unroll
        for (int ks = 0; ks < 8; ks++) {
            int k0 = ks * 8;
            uint2 a0  = *(const uint2*)(aW + k0);
            uint2 a0h = *(const uint2*)(aW + 8 * PADH + k0);
            uint2 a1  = *(const uint2*)(aW + 16 * PADH + k0);
            uint2 a1h = *(const uint2*)(aW + 24 * PADH + k0);
#pragma unroll
            for (int mat = 0; mat < 3; mat++) {
#pragma unroll
                for (int nt = 0; nt < 2; nt++) {
                    uint2 b = *(const uint2*)(bW + (mat * 128 + nt * 8) * PADH + k0);
                    mma_f16(acc[mat][nt][0], a0.x, a0h.x, a0.y, a0h.y, b.x, b.y);
                    mma_f16(acc[mat][nt][1], a1.x, a1h.x, a1.y, a1h.y, b.x, b.y);
                }
            }
        }

        // epilogue: msg = relu(gamma*m + beta) -> fp16
#pragma unroll
        for (int rf = 0; rf < 2; rf++) {
            int ra = row0 + wr * 32 + rf * 16 + g;
            int rb = ra + 8;
#pragma unroll
            for (int nt = 0; nt < 2; nt++) {
                int col = 64 * j + wc * 16 + nt * 8 + 2 * tg;
                const float* m_  = acc[0][nt][rf];
                const float* ga_ = acc[1][nt][rf];
                const float* be_ = acc[2][nt][rf];
                float v0 = fmaxf(fmaf(ga_[0], m_[0], be_[0]), 0.f);
                float v1 = fmaxf(fmaf(ga_[1], m_[1], be_[1]), 0.f);
                float v2 = fmaxf(fmaf(ga_[2], m_[2], be_[2]), 0.f);
                float v3 = fmaxf(fmaf(ga_[3], m_[3], be_[3]), 0.f);
                __half2 ha = __floats2half2_rn(v0, v1);
                __half2 hb = __floats2half2_rn(v2, v3);
                if (ra < N_NODES) g_msg[ra * 64 + (col >> 1)] = ha;
                if (rb < N_NODES) g_msg[rb * 64 + (col >> 1)] = hb;
            }
        }
    }
}

// ==================== output head: sigmoid(hH @ Wp.T + bp), fp16 MMA ====================

__global__ void gemm_out_tc(const float* __restrict__ bp,
                            float* __restrict__ out) {
    extern __shared__ unsigned smem[];
    unsigned* sA = smem;                 // 64*PADH
    unsigned* sB = smem + 64 * PADH;     // 64*PADH

    int tid  = threadIdx.x;   // 256
    int wid  = tid >> 5;
    int lane = tid & 31;
    int g    = lane >> 2;
    int tg   = lane & 3;
    int wr   = wid >> 1;      // 0..3 (16-row group)
    int wc   = wid & 1;       // 0..1 (32-col group)
    int row0 = blockIdx.x * 64;

    unsigned sAu = (unsigned)__cvta_generic_to_shared(sA);
    unsigned sBu = (unsigned)__cvta_generic_to_shared(sB);
#pragma unroll
    for (int t = 0; t < 4; t++) {
        int idx = tid + t * 256;      // 64*16 = 1024
        int r  = idx >> 4;
        int w4 = (idx & 15) * 4;
        cp_async16(sAu + (r * PADH + w4) * 4, g_hH + (row0 + r) * 64 + w4);
        cp_async16(sBu + (r * PADH + w4) * 4, g_BpH + r * 64 + w4);
    }
    CP_COMMIT();
    CP_WAIT0();
    __syncthreads();

    float acc[4][4];
#pragma unroll
    for (int n = 0; n < 4; n++)
#pragma unroll
        for (int q = 0; q < 4; q++) acc[n][q] = 0.f;

    const unsigned* aW = sA + (wr * 16 + g) * PADH + 2 * tg;
#pragma unroll
    for (int ks = 0; ks < 8; ks++) {
        int k0 = ks * 8;
        uint2 a  = *(const uint2*)(aW + k0);
        uint2 ah = *(const uint2*)(aW + 8 * PADH + k0);
#pragma unroll
        for (int nt = 0; nt < 4; nt++) {
            uint2 b = *(const uint2*)(sB + (wc * 32 + nt * 8 + g) * PADH + 2 * tg + k0);
            mma_f16(acc[nt], a.x, ah.x, a.y, ah.y, b.x, b.y);
        }
    }

    int ra = row0 + wr * 16 + g;
    int rb = ra + 8;
#pragma unroll
    for (int nt = 0; nt < 4; nt++) {
        int col = wc * 32 + nt * 8 + 2 * tg;
        float bpv0 = bp[col], bpv1 = bp[col + 1];
        float v0 = 1.f / (1.f + __expf(-(acc[nt][0] + bpv0)));
        float v1 = 1.f / (1.f + __expf(-(acc[nt][1] + bpv1)));
        float v2 = 1.f / (1.f + __expf(-(acc[nt][2] + bpv0)));
        float v3 = 1.f / (1.f + __expf(-(acc[nt][3] + bpv1)));
        if (ra < N_NODES) *(float2*)&out[ra * 64 + col] = make_float2(v0, v1);
        if (rb < N_NODES) *(float2*)&out[rb * 64 + col] = make_float2(v2, v3);
    }
}

// ==================== aggregate + layernorm (fused, warp per node, fp16 in/out) ========
// Output h written as fp16, k-permuted (film/head SMEM operand layout):
// lane owns cols 4l..4l+3 = pairs (2l, 2l+1); group kg=l>>2; slots per (l&3):
// 0->(0,2), 1->(4,6), 2->(1,3), 3->(5,7).

__global__ void aggregate_ln_kernel(const float* __restrict__ gam,
                                    const float* __restrict__ bet) {
    int gw = (blockIdx.x * blockDim.x + threadIdx.x) >> 5;
    int lane = threadIdx.x & 31;
    if (gw >= N_NODES) return;

    int s0 = g_off[gw], s1 = s0 + g_deg[gw];
    const uint2* msg2 = (const uint2*)g_msg;   // 32 uint2 (= 4 halves each) per node row

    float4 acc0 = make_float4(0.f, 0.f, 0.f, 0.f);
    float4 acc1 = make_float4(0.f, 0.f, 0.f, 0.f);
    float4 acc2 = make_float4(0.f, 0.f, 0.f, 0.f);
    float4 acc3 = make_float4(0.f, 0.f, 0.f, 0.f);
    int i = s0;
    for (; i + 4 <= s1; i += 4) {
        int sa = __ldg(&g_csr_src[i]);
        int sb = __ldg(&g_csr_src[i + 1]);
        int sc = __ldg(&g_csr_src[i + 2]);
        int sd = __ldg(&g_csr_src[i + 3]);
        uint2 ua = __ldg(&msg2[sa * 32 + lane]);
        uint2 ub = __ldg(&msg2[sb * 32 + lane]);
        uint2 uc = __ldg(&msg2[sc * 32 + lane]);
        uint2 ud = __ldg(&msg2[sd * 32 + lane]);
        float2 a01 = __half22float2(*(__half2*)&ua.x), a23 = __half22float2(*(__half2*)&ua.y);
        float2 b01 = __half22float2(*(__half2*)&ub.x), b23 = __half22float2(*(__half2*)&ub.y);
        float2 c01 = __half22float2(*(__half2*)&uc.x), c23 = __half22float2(*(__half2*)&uc.y);
        float2 d01 = __half22float2(*(__half2*)&ud.x), d23 = __half22float2(*(__half2*)&ud.y);
        acc0.x += a01.x; acc0.y += a01.y; acc0.z += a23.x; acc0.w += a23.y;
        acc1.x += b01.x; acc1.y += b01.y; acc1.z += b23.x; acc1.w += b23.y;
        acc2.x += c01.x; acc2.y += c01.y; acc2.z += c23.x; acc2.w += c23.y;
        acc3.x += d01.x; acc3.y += d01.y; acc3.z += d23.x; acc3.w += d23.y;
    }
    for (; i < s1; i++) {
        int sa = __ldg(&g_csr_src[i]);
        uint2 ua = __ldg(&msg2[sa * 32 + lane]);
        float2 a01 = __half22float2(*(__half2*)&ua.x), a23 = __half22float2(*(__half2*)&ua.y);
        acc0.x += a01.x; acc0.y += a01.y; acc0.z += a23.x; acc0.w += a23.y;
    }
    float4 acc = make_float4(acc0.x + acc1.x + acc2.x + acc3.x,
                             acc0.y + acc1.y + acc2.y + acc3.y,
                             acc0.z + acc1.z + acc2.z + acc3.z,
                             acc0.w + acc1.w + acc2.w + acc3.w);

    float sum = acc.x + acc.y + acc.z + acc.w;
    float sq  = acc.x * acc.x + acc.y * acc.y + acc.z * acc.z + acc.w * acc.w;
#pragma unroll
    for (int o = 16; o > 0; o >>= 1) {
        sum += __shfl_xor_sync(0xffffffffu, sum, o);
        sq  += __shfl_xor_sync(0xffffffffu, sq,  o);
    }
    float mu  = sum * (1.f / 128.f);
    float var = sq * (1.f / 128.f) - mu * mu;
    float rs  = rsqrtf(var + 1e-5f);

    float4 gv = *(const float4*)&gam[lane * 4];
    float4 bv = *(const float4*)&bet[lane * 4];
    float ox = (acc.x - mu) * rs * gv.x + bv.x;
    float oy = (acc.y - mu) * rs * gv.y + bv.y;
    float oz = (acc.z - mu) * rs * gv.z + bv.z;
    float ow = (acc.w - mu) * rs * gv.w + bv.w;

    int kg = lane >> 2;
    int m  = lane & 3;
    int sA0 = (m == 0) ? 0 : (m == 1) ? 4 : (m == 2) ? 1 : 5;
    __half2* base = g_hH + gw * 64 + kg * 8;
    base[sA0]     = __floats2half2_rn(ox, oy);
    base[sA0 + 2] = __floats2half2_rn(oz, ow);
}

// ============================ launch ============================

extern "C" void kernel_launch(void* const* d_in, const int* in_sizes, int n_in,
                              void* d_out, int out_size) {
    const float* features = (const float*)d_in[0];
    const int*   src      = (const int*)  d_in[1];
    const int*   dst      = (const int*)  d_in[2];
    const float* W1       = (const float*)d_in[3];
    const float* F1       = (const float*)d_in[4];
    const float* g1       = (const float*)d_in[5];
    const float* b1       = (const float*)d_in[6];
    const float* W2       = (const float*)d_in[7];
    const float* F2       = (const float*)d_in[8];
    const float* g2       = (const float*)d_in[9];
    const float* b2       = (const float*)d_in[10];
    const float* Wp       = (const float*)d_in[11];
    const float* bp       = (const float*)d_in[12];
    float* out = (float*)d_out;

    // persistent side stream + events (host resources, created once)
    static cudaStream_t s_side = nullptr;
    static cudaEvent_t  ev_fork = nullptr, ev_join = nullptr, ev_join2 = nullptr;
    if (s_side == nullptr) {
        cudaStreamCreateWithFlags(&s_side, cudaStreamNonBlocking);
        cudaEventCreateWithFlags(&ev_fork,  cudaEventDisableTiming);
        cudaEventCreateWithFlags(&ev_join,  cudaEventDisableTiming);
        cudaEventCreateWithFlags(&ev_join2, cudaEventDisableTiming);
    }

    const int smem_film = (128 * PADH + 384 * PADH) * 4;   // 147456 B
    const int smem_out  = (64 * PADH + 64 * PADH) * 4;     // 36864 B
    cudaFuncSetAttribute(film_gemm_fused, cudaFuncAttributeMaxDynamicSharedMemorySize, smem_film);
    cudaFuncSetAttribute(gemm_out_tc,     cudaFuncAttributeMaxDynamicSharedMemorySize, smem_out);

    dim3 film_grid((N_NODES + 127) / 128);
    dim3 agg_grid((N_NODES + 7) / 8);

    // fork side branch off the capture-origin stream
    cudaEventRecord(ev_fork, 0);
    cudaStreamWaitEvent(s_side, ev_fork, 0);

    // branch B (side stream): CSR build -> ev_join; then layer-2/head prep -> ev_join2
    zero_deg_kernel<<<(N_NODES + 255) / 256, 256, 0, s_side>>>();
    hist_kernel<<<(N_EDGES + 255) / 256, 256, 0, s_side>>>(dst);
    offsets_kernel<<<(N_NODES + 255) / 256, 256, 0, s_side>>>();
    fill_csr_kernel<<<(N_EDGES + 255) / 256, 256, 0, s_side>>>(src, dst);
    cudaEventRecord(ev_join, s_side);
    prep_weights<<<(384 * 8 + 255) / 256, 256, 0, s_side>>>(W2, F2, 1);
    prep_wp<<<(64 * 8 + 255) / 256, 256, 0, s_side>>>(Wp);
    cudaEventRecord(ev_join2, s_side);

    // branch A (origin stream): layer-1 prep + GEMM
    prep_weights<<<(384 * 8 + 255) / 256, 256>>>(W1, F1, 0);
    film_gemm_fused<<<film_grid, 512, smem_film>>>(features, 0);

    // join: aggregation needs CSR + msg
    cudaStreamWaitEvent(0, ev_join, 0);
    aggregate_ln_kernel<<<agg_grid, 256>>>(g1, b1);

    // layer 2 (needs g_BtH2 from side stream)
    cudaStreamWaitEvent(0, ev_join2, 0);
    film_gemm_fused<<<film_grid, 512, smem_film>>>(nullptr, 1);
    aggregate_ln_kernel<<<agg_grid, 256>>>(g2, b2);

    // output head
    gemm_out_tc<<<(N_NODES + 63) / 64, 256, smem_out>>>(bp, out);
}

// round 12
// speedup vs baseline: 1.4092x; 1.0240x over previous
#include <cuda_runtime.h>
#include <cuda_fp16.h>

#define N_NODES 50000
#define N_EDGES 600000
#define NPAD    50048   // padded row count for raw tile copies
#define DIM 128
#define OUTD 64

#define PADH 72    // fp16 rows: 64 data words (128 halves) + 8 pad; mod 32 = 8 -> conflict-free

// ---- scratch (static device globals; no runtime allocation) ----
__device__ __half2   g_msg[N_NODES * 64];   // fp16 messages (128 per node)
__device__ __align__(16) __half2 g_hH[NPAD * 64];  // fp16 hidden state, k-permuted
__device__ int       g_deg[N_NODES];
__device__ int       g_off[N_NODES];
__device__ int       g_cur[N_NODES];
__device__ int       g_ctr;
__device__ int       g_csr_src[N_EDGES];
// fp16 weight panels, k-permuted, usage order: row p = mat*128 + c;
// mat0: W[c] (m), mat1: F[c] (gamma), mat2: F[128+c] (beta). 64 half2-words per row.
__device__ __align__(16) __half2 g_BtH1[384 * 64];
__device__ __align__(16) __half2 g_BtH2[384 * 64];
__device__ __align__(16) __half2 g_BpH[64 * 64];   // Wp fp16, k-permuted

// ============================ helpers ============================

__device__ __forceinline__ unsigned h2u(__half2 h) {
    return *(unsigned*)&h;
}

__device__ __forceinline__ void griddep_wait() {
    asm volatile("griddepcontrol.wait;" ::: "memory");
}

__device__ __forceinline__ void mma_f16(float* c,
                                        unsigned a0, unsigned a1, unsigned a2, unsigned a3,
                                        unsigned b0, unsigned b1) {
    asm volatile(
        "mma.sync.aligned.m16n8k16.row.col.f32.f16.f16.f32 "
        "{%0,%1,%2,%3}, {%4,%5,%6,%7}, {%8,%9}, {%0,%1,%2,%3};"
        : "+f"(c[0]), "+f"(c[1]), "+f"(c[2]), "+f"(c[3])
        : "r"(a0), "r"(a1), "r"(a2), "r"(a3), "r"(b0), "r"(b1));
}

__device__ __forceinline__ void cp_async16(unsigned smem_addr, const void* gptr) {
    asm volatile("cp.async.cg.shared.global [%0], [%1], 16;"
                 :: "r"(smem_addr), "l"(gptr));
}
#define CP_COMMIT() asm volatile("cp.async.commit_group;" ::: "memory")
#define CP_WAIT0()  asm volatile("cp.async.wait_group 0;" ::: "memory")

// ============================ CSR build ============================

__global__ void zero_deg_kernel() {
    int i = blockIdx.x * blockDim.x + threadIdx.x;
    if (i < N_NODES) g_deg[i] = 0;
    if (i == 0) g_ctr = 0;
}

__global__ void hist_kernel(const int* __restrict__ dst) {
    int e = blockIdx.x * blockDim.x + threadIdx.x;
    if (e < N_EDGES) atomicAdd(&g_deg[dst[e]], 1);
}

// unordered disjoint range claim (aggregation is order-agnostic)
__global__ void offsets_kernel() {
    int i = blockIdx.x * blockDim.x + threadIdx.x;
    if (i < N_NODES) {
        int d = g_deg[i];
        int s = atomicAdd(&g_ctr, d);
        g_off[i] = s;
        g_cur[i] = s;
    }
}

__global__ void fill_csr_kernel(const int* __restrict__ src, const int* __restrict__ dst) {
    int e = blockIdx.x * blockDim.x + threadIdx.x;
    if (e < N_EDGES) {
        int d = dst[e];
        int p = atomicAdd(&g_cur[d], 1);
        g_csr_src[p] = src[e];
    }
}

// ==================== weight prep (fp32 -> fp16, k-permuted 16-groups) ====================

__global__ void prep_weights(const float* __restrict__ W,
                             const float* __restrict__ F,
                             int layer) {
    __half2* dst = layer ? g_BtH2 : g_BtH1;
    int idx = blockIdx.x * blockDim.x + threadIdx.x;   // over 384 rows x 8 kgroups
    if (idx >= 384 * 8) return;
    int p  = idx >> 3;
    int kg = idx & 7;
    int mat = p >> 7, c = p & 127;
    const float* srcRow = (mat == 0) ? W + c * 128
                        : (mat == 1) ? F + c * 128
                                     : F + (128 + c) * 128;
    const float* s = srcRow + kg * 16;
    float4 f0 = *(const float4*)(s);
    float4 f1 = *(const float4*)(s + 4);
    float4 f2 = *(const float4*)(s + 8);
    float4 f3 = *(const float4*)(s + 12);
    uint4 q0 = make_uint4(h2u(__floats2half2_rn(f0.x, f0.y)),
                          h2u(__floats2half2_rn(f2.x, f2.y)),
                          h2u(__floats2half2_rn(f0.z, f0.w)),
                          h2u(__floats2half2_rn(f2.z, f2.w)));
    uint4 q1 = make_uint4(h2u(__floats2half2_rn(f1.x, f1.y)),
                          h2u(__floats2half2_rn(f3.x, f3.y)),
                          h2u(__floats2half2_rn(f1.z, f1.w)),
                          h2u(__floats2half2_rn(f3.z, f3.w)));
    uint4* d = (uint4*)(dst + p * 64 + kg * 8);
    d[0] = q0;
    d[1] = q1;
}

__global__ void prep_wp(const float* __restrict__ Wp) {
    int idx = blockIdx.x * blockDim.x + threadIdx.x;   // over 64 rows x 8 kgroups
    if (idx >= 64 * 8) return;
    int p  = idx >> 3;
    int kg = idx & 7;
    const float* s = Wp + p * 128 + kg * 16;
    float4 f0 = *(const float4*)(s);
    float4 f1 = *(const float4*)(s + 4);
    float4 f2 = *(const float4*)(s + 8);
    float4 f3 = *(const float4*)(s + 12);
    uint4 q0 = make_uint4(h2u(__floats2half2_rn(f0.x, f0.y)),
                          h2u(__floats2half2_rn(f2.x, f2.y)),
                          h2u(__floats2half2_rn(f0.z, f0.w)),
                          h2u(__floats2half2_rn(f2.z, f2.w)));
    uint4 q1 = make_uint4(h2u(__floats2half2_rn(f1.x, f1.y)),
                          h2u(__floats2half2_rn(f3.x, f3.y)),
                          h2u(__floats2half2_rn(f1.z, f1.w)),
                          h2u(__floats2half2_rn(f3.z, f3.w)));
    uint4* d = (uint4*)(g_BpH + p * 64 + kg * 8);
    d[0] = q0;
    d[1] = q1;
}

// ==================== fused FiLM GEMM (fp16 m16n8k16, M=128, 512 thr, PDL) ==============
// layer 0: A-convert (features, independent) PRE-wait; weights (prep1 output) POST-wait.
// layer 1: weight staging (ready via event edge) PRE-wait; A copy (g_hH from agg1) POST-wait.

__global__ void film_gemm_fused(const float* __restrict__ Ain, int layer) {
    extern __shared__ unsigned smem[];
    unsigned* sA = smem;                   // 128*PADH (fp16, k-permuted)
    unsigned* sB = smem + 128 * PADH;      // 384*PADH (full weight panel)

    const __half2* Bt = layer ? g_BtH2 : g_BtH1;

    int tid  = threadIdx.x;     // 512
    int wid  = tid >> 5;
    int lane = tid & 31;
    int g    = lane >> 2;       // 0..7
    int tg   = lane & 3;        // 0..3
    int wr   = wid >> 2;        // 0..3 (32-row group)
    int wc   = wid & 3;         // 0..3 (16-col group per mat per j)
    int row0 = blockIdx.x * 128;

    unsigned sBu = (unsigned)__cvta_generic_to_shared(sB);

    if (layer) {
        // weight panel pre-wait (g_BtH2 guaranteed by event edge)
#pragma unroll
        for (int t = 0; t < 12; t++) {
            int idx = tid + t * 512;
            int r  = idx >> 4;
            int w4 = (idx & 15) * 4;
            cp_async16(sBu + (r * PADH + w4) * 4, Bt + r * 64 + w4);
        }
        griddep_wait();   // wait for agg1: g_hH ready
        unsigned sAu = (unsigned)__cvta_generic_to_shared(sA);
#pragma unroll
        for (int t = 0; t < 4; t++) {
            int idx = tid + t * 512;     // 128*16 = 2048
            int r  = idx >> 4;
            int w4 = (idx & 15) * 4;
            cp_async16(sAu + (r * PADH + w4) * 4, g_hH + (row0 + r) * 64 + w4);
        }
        CP_COMMIT();
    } else {
        // convert A tile fp32 -> fp16, k-permuted (features: independent of prep1)
        for (int idx = tid; idx < 128 * 8; idx += 512) {
            int r  = idx >> 3;
            int kg = idx & 7;
            int grow = row0 + r;
            float4 f0, f1, f2, f3;
            if (grow < N_NODES) {
                const float* s = Ain + grow * 128 + kg * 16;
                f0 = *(const float4*)(s);
                f1 = *(const float4*)(s + 4);
                f2 = *(const float4*)(s + 8);
                f3 = *(const float4*)(s + 12);
            } else {
                f0 = make_float4(0.f, 0.f, 0.f, 0.f);
                f1 = f0; f2 = f0; f3 = f0;
            }
            uint4 q0 = make_uint4(h2u(__floats2half2_rn(f0.x, f0.y)),
                                  h2u(__floats2half2_rn(f2.x, f2.y)),
                                  h2u(__floats2half2_rn(f0.z, f0.w)),
                                  h2u(__floats2half2_rn(f2.z, f2.w)));
            uint4 q1 = make_uint4(h2u(__floats2half2_rn(f1.x, f1.y)),
                                  h2u(__floats2half2_rn(f3.x, f3.y)),
                                  h2u(__floats2half2_rn(f1.z, f1.w)),
                                  h2u(__floats2half2_rn(f3.z, f3.w)));
            unsigned* p = sA + r * PADH + kg * 8;
            *(uint4*)(p)     = q0;
            *(uint4*)(p + 4) = q1;
        }
        griddep_wait();   // wait for prep1: g_BtH1 ready
#pragma unroll
        for (int t = 0; t < 12; t++) {
            int idx = tid + t * 512;
            int r  = idx >> 4;
            int w4 = (idx & 15) * 4;
            cp_async16(sBu + (r * PADH + w4) * 4, Bt + r * 64 + w4);
        }
        CP_COMMIT();
    }

    CP_WAIT0();
    __syncthreads();

    const unsigned* aW = sA + (wr * 32 + g) * PADH + 2 * tg;

#pragma unroll
    for (int j = 0; j < 2; j++) {
        float acc[3][2][2][4];   // [mat][nt][row-frag][quad]
#pragma unroll
        for (int m = 0; m < 3; m++)
#pragma unroll
            for (int n = 0; n < 2; n++)
#pragma unroll
                for (int rf = 0; rf < 2; rf++)
#pragma unroll
                    for (int q = 0; q < 4; q++) acc[m][n][rf][q] = 0.f;

        const unsigned* bW = sB + (j * 64 + wc * 16 + g) * PADH + 2 * tg;

#pragma unroll
        for (int ks = 0; ks < 8; ks++) {
            int k0 = ks * 8;
            uint2 a0  = *(const uint2*)(aW + k0);
            uint2 a0h = *(const uint2*)(aW + 8 * PADH + k0);
            uint2 a1  = *(const uint2*)(aW + 16 * PADH + k0);
            uint2 a1h = *(const uint2*)(aW + 24 * PADH + k0);
#pragma unroll
            for (int mat = 0; mat < 3; mat++) {
#pragma unroll
                for (int nt = 0; nt < 2; nt++) {
                    uint2 b = *(const uint2*)(bW + (mat * 128 + nt * 8) * PADH + k0);
                    mma_f16(acc[mat][nt][0], a0.x, a0h.x, a0.y, a0h.y, b.x, b.y);
                    mma_f16(acc[mat][nt][1], a1.x, a1h.x, a1.y, a1h.y, b.x, b.y);
                }
            }
        }

        // epilogue: msg = relu(gamma*m + beta) -> fp16
#pragma unroll
        for (int rf = 0; rf < 2; rf++) {
            int ra = row0 + wr * 32 + rf * 16 + g;
            int rb = ra + 8;
#pragma unroll
            for (int nt = 0; nt < 2; nt++) {
                int col = 64 * j + wc * 16 + nt * 8 + 2 * tg;
                const float* m_  = acc[0][nt][rf];
                const float* ga_ = acc[1][nt][rf];
                const float* be_ = acc[2][nt][rf];
                float v0 = fmaxf(fmaf(ga_[0], m_[0], be_[0]), 0.f);
                float v1 = fmaxf(fmaf(ga_[1], m_[1], be_[1]), 0.f);
                float v2 = fmaxf(fmaf(ga_[2], m_[2], be_[2]), 0.f);
                float v3 = fmaxf(fmaf(ga_[3], m_[3], be_[3]), 0.f);
                __half2 ha = __floats2half2_rn(v0, v1);
                __half2 hb = __floats2half2_rn(v2, v3);
                if (ra < N_NODES) g_msg[ra * 64 + (col >> 1)] = ha;
                if (rb < N_NODES) g_msg[rb * 64 + (col >> 1)] = hb;
            }
        }
    }
}

// ==================== output head: sigmoid(hH @ Wp.T + bp), fp16 MMA, PDL ================

__global__ void gemm_out_tc(const float* __restrict__ bp,
                            float* __restrict__ out) {
    extern __shared__ unsigned smem[];
    unsigned* sA = smem;                 // 64*PADH
    unsigned* sB = smem + 64 * PADH;     // 64*PADH

    int tid  = threadIdx.x;   // 256
    int wid  = tid >> 5;
    int lane = tid & 31;
    int g    = lane >> 2;
    int tg   = lane & 3;
    int wr   = wid >> 1;      // 0..3 (16-row group)
    int wc   = wid & 1;       // 0..1 (32-col group)
    int row0 = blockIdx.x * 64;

    unsigned sAu = (unsigned)__cvta_generic_to_shared(sA);
    unsigned sBu = (unsigned)__cvta_generic_to_shared(sB);
    // Wp panel pre-wait (independent of agg2)
#pragma unroll
    for (int t = 0; t < 4; t++) {
        int idx = tid + t * 256;      // 64*16 = 1024
        int r  = idx >> 4;
        int w4 = (idx & 15) * 4;
        cp_async16(sBu + (r * PADH + w4) * 4, g_BpH + r * 64 + w4);
    }
    griddep_wait();   // wait for agg2: g_hH ready
#pragma unroll
    for (int t = 0; t < 4; t++) {
        int idx = tid + t * 256;
        int r  = idx >> 4;
        int w4 = (idx & 15) * 4;
        cp_async16(sAu + (r * PADH + w4) * 4, g_hH + (row0 + r) * 64 + w4);
    }
    CP_COMMIT();
    CP_WAIT0();
    __syncthreads();

    float acc[4][4];
#pragma unroll
    for (int n = 0; n < 4; n++)
#pragma unroll
        for (int q = 0; q < 4; q++) acc[n][q] = 0.f;

    const unsigned* aW = sA + (wr * 16 + g) * PADH + 2 * tg;
#pragma unroll
    for (int ks = 0; ks < 8; ks++) {
        int k0 = ks * 8;
        uint2 a  = *(const uint2*)(aW + k0);
        uint2 ah = *(const uint2*)(aW + 8 * PADH + k0);
#pragma unroll
        for (int nt = 0; nt < 4; nt++) {
            uint2 b = *(const uint2*)(sB + (wc * 32 + nt * 8 + g) * PADH + 2 * tg + k0);
            mma_f16(acc[nt], a.x, ah.x, a.y, ah.y, b.x, b.y);
        }
    }

    int ra = row0 + wr * 16 + g;
    int rb = ra + 8;
#pragma unroll
    for (int nt = 0; nt < 4; nt++) {
        int col = wc * 32 + nt * 8 + 2 * tg;
        float bpv0 = bp[col], bpv1 = bp[col + 1];
        float v0 = 1.f / (1.f + __expf(-(acc[nt][0] + bpv0)));
        float v1 = 1.f / (1.f + __expf(-(acc[nt][1] + bpv1)));
        float v2 = 1.f / (1.f + __expf(-(acc[nt][2] + bpv0)));
        float v3 = 1.f / (1.f + __expf(-(acc[nt][3] + bpv1)));
        if (ra < N_NODES) *(float2*)&out[ra * 64 + col] = make_float2(v0, v1);
        if (rb < N_NODES) *(float2*)&out[rb * 64 + col] = make_float2(v2, v3);
    }
}

// ==================== aggregate + layernorm (fused, warp per node, fp16 in/out, PDL) =====

__global__ void aggregate_ln_kernel(const float* __restrict__ gam,
                                    const float* __restrict__ bet) {
    int gw = (blockIdx.x * blockDim.x + threadIdx.x) >> 5;
    int lane = threadIdx.x & 31;
    if (gw >= N_NODES) return;

    // CSR from branch B (event-gated at launch) readable pre-wait
    int s0 = g_off[gw], s1 = s0 + g_deg[gw];
    griddep_wait();   // wait for producing film kernel: g_msg ready

    const uint2* msg2 = (const uint2*)g_msg;   // 32 uint2 (= 4 halves each) per node row

    float4 acc0 = make_float4(0.f, 0.f, 0.f, 0.f);
    float4 acc1 = make_float4(0.f, 0.f, 0.f, 0.f);
    float4 acc2 = make_float4(0.f, 0.f, 0.f, 0.f);
    float4 acc3 = make_float4(0.f, 0.f, 0.f, 0.f);
    int i = s0;
    for (; i + 4 <= s1; i += 4) {
        int sa = __ldg(&g_csr_src[i]);
        int sb = __ldg(&g_csr_src[i + 1]);
        int sc = __ldg(&g_csr_src[i + 2]);
        int sd = __ldg(&g_csr_src[i + 3]);
        uint2 ua = __ldg(&msg2[sa * 32 + lane]);
        uint2 ub = __ldg(&msg2[sb * 32 + lane]);
        uint2 uc = __ldg(&msg2[sc * 32 + lane]);
        uint2 ud = __ldg(&msg2[sd * 32 + lane]);
        float2 a01 = __half22float2(*(__half2*)&ua.x), a23 = __half22float2(*(__half2*)&ua.y);
        float2 b01 = __half22float2(*(__half2*)&ub.x), b23 = __half22float2(*(__half2*)&ub.y);
        float2 c01 = __half22float2(*(__half2*)&uc.x), c23 = __half22float2(*(__half2*)&uc.y);
        float2 d01 = __half22float2(*(__half2*)&ud.x), d23 = __half22float2(*(__half2*)&ud.y);
        acc0.x += a01.x; acc0.y += a01.y; acc0.z += a23.x; acc0.w += a23.y;
        acc1.x += b01.x; acc1.y += b01.y; acc1.z += b23.x; acc1.w += b23.y;
        acc2.x += c01.x; acc2.y += c01.y; acc2.z += c23.x; acc2.w += c23.y;
        acc3.x += d01.x; acc3.y += d01.y; acc3.z += d23.x; acc3.w += d23.y;
    }
    for (; i < s1; i++) {
        int sa = __ldg(&g_csr_src[i]);
        uint2 ua = __ldg(&msg2[sa * 32 + lane]);
        float2 a01 = __half22float2(*(__half2*)&ua.x), a23 = __half22float2(*(__half2*)&ua.y);
        acc0.x += a01.x; acc0.y += a01.y; acc0.z += a23.x; acc0.w += a23.y;
    }
    float4 acc = make_float4(acc0.x + acc1.x + acc2.x + acc3.x,
                             acc0.y + acc1.y + acc2.y + acc3.y,
                             acc0.z + acc1.z + acc2.z + acc3.z,
                             acc0.w + acc1.w + acc2.w + acc3.w);

    float sum = acc.x + acc.y + acc.z + acc.w;
    float sq  = acc.x * acc.x + acc.y * acc.y + acc.z * acc.z + acc.w * acc.w;
#pragma unroll
    for (int o = 16; o > 0; o >>= 1) {
        sum += __shfl_xor_sync(0xffffffffu, sum, o);
        sq  += __shfl_xor_sync(0xffffffffu, sq,  o);
    }
    float mu  = sum * (1.f / 128.f);
    float var = sq * (1.f / 128.f) - mu * mu;
    float rs  = rsqrtf(var + 1e-5f);

    float4 gv = *(const float4*)&gam[lane * 4];
    float4 bv = *(const float4*)&bet[lane * 4];
    float ox = (acc.x - mu) * rs * gv.x + bv.x;
    float oy = (acc.y - mu) * rs * gv.y + bv.y;
    float oz = (acc.z - mu) * rs * gv.z + bv.z;
    float ow = (acc.w - mu) * rs * gv.w + bv.w;

    // fp16 k-permuted store (film/head SMEM operand layout)
    int kg = lane >> 2;
    int m  = lane & 3;
    int sA0 = (m == 0) ? 0 : (m == 1) ? 4 : (m == 2) ? 1 : 5;
    __half2* base = g_hH + gw * 64 + kg * 8;
    base[sA0]     = __floats2half2_rn(ox, oy);
    base[sA0 + 2] = __floats2half2_rn(oz, ow);
}

// ============================ launch ============================

template <typename F, typename... Args>
static void launch_pdl(dim3 grid, dim3 block, size_t smem, F kernel, Args... args) {
    cudaLaunchConfig_t cfg = {};
    cfg.gridDim = grid;
    cfg.blockDim = block;
    cfg.dynamicSmemBytes = smem;
    cfg.stream = 0;
    cudaLaunchAttribute attr[1];
    attr[0].id = cudaLaunchAttributeProgrammaticStreamSerialization;
    attr[0].val.programmaticStreamSerializationAllowed = 1;
    cfg.attrs = attr;
    cfg.numAttrs = 1;
    cudaLaunchKernelEx(&cfg, kernel, args...);
}

extern "C" void kernel_launch(void* const* d_in, const int* in_sizes, int n_in,
                              void* d_out, int out_size) {
    const float* features = (const float*)d_in[0];
    const int*   src      = (const int*)  d_in[1];
    const int*   dst      = (const int*)  d_in[2];
    const float* W1       = (const float*)d_in[3];
    const float* F1       = (const float*)d_in[4];
    const float* g1       = (const float*)d_in[5];
    const float* b1       = (const float*)d_in[6];
    const float* W2       = (const float*)d_in[7];
    const float* F2       = (const float*)d_in[8];
    const float* g2       = (const float*)d_in[9];
    const float* b2       = (const float*)d_in[10];
    const float* Wp       = (const float*)d_in[11];
    const float* bp       = (const float*)d_in[12];
    float* out = (float*)d_out;

    // persistent side stream + events (host resources, created once)
    static cudaStream_t s_side = nullptr;
    static cudaEvent_t  ev_fork = nullptr, ev_join = nullptr, ev_join2 = nullptr;
    if (s_side == nullptr) {
        cudaStreamCreateWithFlags(&s_side, cudaStreamNonBlocking);
        cudaEventCreateWithFlags(&ev_fork,  cudaEventDisableTiming);
        cudaEventCreateWithFlags(&ev_join,  cudaEventDisableTiming);
        cudaEventCreateWithFlags(&ev_join2, cudaEventDisableTiming);
    }

    const int smem_film = (128 * PADH + 384 * PADH) * 4;   // 147456 B
    const int smem_out  = (64 * PADH + 64 * PADH) * 4;     // 36864 B
    cudaFuncSetAttribute(film_gemm_fused, cudaFuncAttributeMaxDynamicSharedMemorySize, smem_film);
    cudaFuncSetAttribute(gemm_out_tc,     cudaFuncAttributeMaxDynamicSharedMemorySize, smem_out);

    dim3 film_grid((N_NODES + 127) / 128);
    dim3 agg_grid((N_NODES + 7) / 8);

    // fork side branch off the capture-origin stream
    cudaEventRecord(ev_fork, 0);
    cudaStreamWaitEvent(s_side, ev_fork, 0);

    // branch B (side stream): CSR build -> ev_join; then layer-2/head prep -> ev_join2
    zero_deg_kernel<<<(N_NODES + 255) / 256, 256, 0, s_side>>>();
    hist_kernel<<<(N_EDGES + 255) / 256, 256, 0, s_side>>>(dst);
    offsets_kernel<<<(N_NODES + 255) / 256, 256, 0, s_side>>>();
    fill_csr_kernel<<<(N_EDGES + 255) / 256, 256, 0, s_side>>>(src, dst);
    cudaEventRecord(ev_join, s_side);
    prep_weights<<<(384 * 8 + 255) / 256, 256, 0, s_side>>>(W2, F2, 1);
    prep_wp<<<(64 * 8 + 255) / 256, 256, 0, s_side>>>(Wp);
    cudaEventRecord(ev_join2, s_side);

    // branch A (origin stream): layer-1 prep, then PDL chain
    prep_weights<<<(384 * 8 + 255) / 256, 256>>>(W1, F1, 0);

    // film1: PDL over prep1 (A-convert from features runs pre-wait)
    launch_pdl(film_grid, dim3(512), (size_t)smem_film,
               film_gemm_fused, features, 0);

    // agg1: needs CSR (event) + msg (PDL over film1)
    cudaStreamWaitEvent(0, ev_join, 0);
    launch_pdl(agg_grid, dim3(256), (size_t)0,
               aggregate_ln_kernel, g1, b1);

    // film2: needs g_BtH2 (event) + g_hH (PDL over agg1; weight staging pre-wait)
    cudaStreamWaitEvent(0, ev_join2, 0);
    launch_pdl(film_grid, dim3(512), (size_t)smem_film,
               film_gemm_fused, (const float*)nullptr, 1);

    // agg2: PDL over film2
    launch_pdl(agg_grid, dim3(256), (size_t)0,
               aggregate_ln_kernel, g2, b2);

    // head: PDL over agg2 (Wp staging pre-wait)
    launch_pdl(dim3((N_NODES + 63) / 64), dim3(256), (size_t)smem_out,
               gemm_out_tc, bp, out);
}